// round 11
// baseline (speedup 1.0000x reference)
#include <cuda_runtime.h>

// Fixed problem shape: B=16, C=1, H=128, W=8192, NMAX=64
#define BB   16
#define HH   128
#define WW   8192
#define NMX  64
#define TILE_COLS 1024
#define TILE_ROWS 4             // grid.z = 32 -> 4096 blocks
#define BIGV 0x3FFFFFFF

// Scratch for segment metadata (allocation-free rule: device globals)
__device__ int g_start[BB][NMX];
__device__ int g_end[BB][NMX];
__device__ int g_src0[BB][NMX];
__device__ int g_n[BB];

// ---------------------------------------------------------------------------
// Kernel 1: per-batch metadata. 16 blocks x 64 threads.
// ---------------------------------------------------------------------------
__global__ void meta_kernel(const int* __restrict__ xi,
                            const int* __restrict__ N,
                            float* __restrict__ out_xi,
                            int write_xi) {
    const int b = blockIdx.x;
    const int i = threadIdx.x;            // 0..63
    __shared__ int sh_w0;

    const int n = N[b];
    const int s = xi[(b * NMX + i) * 2 + 0];
    const int e = xi[(b * NMX + i) * 2 + 1];
    const int valid = (i < n) ? 1 : 0;
    const int wv = valid ? max(e - s, 0) : 0;

    int sc = wv;
    #pragma unroll
    for (int off = 1; off < 32; off <<= 1) {
        int v = __shfl_up_sync(0xFFFFFFFFu, sc, off);
        if ((i & 31) >= off) sc += v;
    }
    if (i == 31) sh_w0 = sc;
    __syncthreads();
    const int csum = sc + ((i >= 32) ? sh_w0 : 0);
    const int sn = csum - wv + i;
    const int en = csum + i;

    g_start[b][i] = valid ? sn : BIGV;
    g_end[b][i]   = en;
    g_src0[b][i]  = s;
    if (i == 0) g_n[b] = n;

    if (write_xi) {
        out_xi[(b * NMX + i) * 2 + 0] = valid ? (float)sn : 0.0f;
        out_xi[(b * NMX + i) * 2 + 1] = valid ? (float)en : 0.0f;
    }
}

// ---------------------------------------------------------------------------
// Kernel 2: pack/gather with SMEM transpose to kill L1tex wavefront replays.
// grid = (WW/1024=8, BB=16, HH/4=32) = 4096 blocks, block = 256.
// Phase A: thread t gathers columns base+t+256k (k=0..3) for 4 rows --
//          lane-consecutive addresses -> 1 line per LDG (no replays) --
//          and stages them in shared memory.
// Phase B: thread t reads smem float4 (cols 4t..4t+3) per row and does one
//          coalesced STG.128 per row.
// s_tile MUST be 16B-aligned (float4 LDS) -- round 10 crashed on this.
// ---------------------------------------------------------------------------
__global__ void __launch_bounds__(256)
pack_kernel(const float* __restrict__ x,
            const float* __restrict__ sep_param,
            float* __restrict__ out) {
    const int b = blockIdx.y;
    const int t = threadIdx.x;

    __shared__ __align__(16) float s_tile[TILE_ROWS * TILE_COLS];  // 16 KB
    __shared__ int   s_start[NMX + 1];
    __shared__ int   s_end[NMX];
    __shared__ int   s_src[NMX];
    __shared__ int   s_n;
    __shared__ float s_sep;

    if (t < NMX) {
        s_start[t] = g_start[b][t];
        s_end[t]   = g_end[b][t];
        s_src[t]   = g_src0[b][t];
    }
    if (t == 0) { s_n = g_n[b]; s_sep = sep_param[0]; s_start[NMX] = BIGV; }
    __syncthreads();

    const int n       = s_n;
    const int colbase = blockIdx.x * TILE_COLS;

    // Classify 4 columns, 256 apart (coalesced-load assignment).
    int   off[4];
    float fval[4];
    #pragma unroll
    for (int k = 0; k < 4; k++) {
        const int j = colbase + t + 256 * k;
        int lo = 0, hi = n;
        while (lo < hi) {
            int mid = (lo + hi) >> 1;
            if (s_start[mid] <= j) lo = mid + 1; else hi = mid;
        }
        const int cur = lo - 1;
        const int s = s_start[cur];
        const int e = s_end[cur];
        int   o = -1;
        float f = 0.0f;
        if (j < e)                      o = s_src[cur] + (j - s);
        else if (j == e && cur < n - 1) f = s_sep;
        off[k]  = o;
        fval[k] = f;
    }

    const int h0 = blockIdx.z * TILE_ROWS;
    const float* __restrict__ xb = x   + (size_t)b * HH * WW + (size_t)h0 * WW;
    float* __restrict__       ob = out + (size_t)b * HH * WW + (size_t)h0 * WW
                                       + colbase;

    // ---- Phase A: coalesced gather -> smem (16 independent LDGs) ----
    #pragma unroll
    for (int r = 0; r < TILE_ROWS; r++) {
        const size_t row = (size_t)r * WW;
        #pragma unroll
        for (int k = 0; k < 4; k++) {
            const float v = (off[k] >= 0) ? __ldg(xb + row + off[k]) : fval[k];
            s_tile[r * TILE_COLS + t + 256 * k] = v;
        }
    }
    __syncthreads();

    // ---- Phase B: float4 from smem -> coalesced STG.128 ----
    #pragma unroll
    for (int r = 0; r < TILE_ROWS; r++) {
        const float4 v = *reinterpret_cast<const float4*>(
            &s_tile[r * TILE_COLS + 4 * t]);
        __stcs(reinterpret_cast<float4*>(ob + (size_t)r * WW + 4 * t), v);
    }
}

// ---------------------------------------------------------------------------
extern "C" void kernel_launch(void* const* d_in, const int* in_sizes, int n_in,
                              void* d_out, int out_size) {
    const float* x   = (const float*)d_in[0];
    const int*   xi  = (const int*)  d_in[1];
    const int*   N   = (const int*)  d_in[2];
    const float* sep = (const float*)d_in[3];
    float*       out = (float*)d_out;

    const long long XN = (long long)BB * HH * WW;   // 16,777,216
    const int write_xi = ((long long)out_size > XN) ? 1 : 0;

    meta_kernel<<<BB, NMX>>>(xi, N, out + XN, write_xi);

    dim3 grid(WW / TILE_COLS, BB, HH / TILE_ROWS);
    pack_kernel<<<grid, 256>>>(x, sep, out);
}

// round 12
// speedup vs baseline: 1.1825x; 1.1825x over previous
#include <cuda_runtime.h>

// Fixed problem shape: B=16, C=1, H=128, W=8192, NMAX=64
#define BB   16
#define HH   128
#define WW   8192
#define NMX  64
#define ROWS_PER_BLOCK 8        // grid.z = 16 -> 2048 pack blocks
#define BIGV 0x3FFFFFFF

// Scratch (allocation-free rule: device globals)
__device__ int g_start[BB][NMX];
__device__ int g_end[BB][NMX];
__device__ int g_src0[BB][NMX];
__device__ int g_n[BB];
__device__ int g_map[BB][WW];    // per-column: >=0 src, -1 sep, -2 zero

// ---------------------------------------------------------------------------
// Kernel 1: per-batch metadata. 16 blocks x 64 threads. Prefix-scan of chirp
// widths -> compressed starts/ends; writes xi_new to output tail.
// ---------------------------------------------------------------------------
__global__ void meta_kernel(const int* __restrict__ xi,
                            const int* __restrict__ N,
                            float* __restrict__ out_xi,
                            int write_xi) {
    const int b = blockIdx.x;
    const int i = threadIdx.x;            // 0..63
    __shared__ int sh_w0;

    const int n = N[b];
    const int s = xi[(b * NMX + i) * 2 + 0];
    const int e = xi[(b * NMX + i) * 2 + 1];
    const int valid = (i < n) ? 1 : 0;
    const int wv = valid ? max(e - s, 0) : 0;

    int sc = wv;
    #pragma unroll
    for (int off = 1; off < 32; off <<= 1) {
        int v = __shfl_up_sync(0xFFFFFFFFu, sc, off);
        if ((i & 31) >= off) sc += v;
    }
    if (i == 31) sh_w0 = sc;
    __syncthreads();
    const int csum = sc + ((i >= 32) ? sh_w0 : 0);
    const int sn = csum - wv + i;
    const int en = csum + i;

    g_start[b][i] = valid ? sn : BIGV;
    g_end[b][i]   = en;
    g_src0[b][i]  = s;
    if (i == 0) g_n[b] = n;

    if (write_xi) {
        out_xi[(b * NMX + i) * 2 + 0] = valid ? (float)sn : 0.0f;
        out_xi[(b * NMX + i) * 2 + 1] = valid ? (float)en : 0.0f;
    }
}

// ---------------------------------------------------------------------------
// Kernel 2: build per-column source map. grid = (16, 8), block = 256.
// Each thread classifies 4 consecutive columns with ONE binary search
// (segments contiguous, min extent > 4). Writes int4.
// ---------------------------------------------------------------------------
__global__ void __launch_bounds__(256)
map_kernel(void) {
    const int b = blockIdx.x;
    const int t = threadIdx.x;

    __shared__ int   s_start[NMX + 1];
    __shared__ int   s_end[NMX];
    __shared__ int   s_src[NMX];
    __shared__ int   s_n;

    if (t < NMX) {
        s_start[t] = g_start[b][t];
        s_end[t]   = g_end[b][t];
        s_src[t]   = g_src0[b][t];
    }
    if (t == 0) { s_n = g_n[b]; s_start[NMX] = BIGV; }
    __syncthreads();

    const int n  = s_n;
    const int j0 = (blockIdx.y * 256 + t) * 4;

    int lo = 0, hi = n;
    while (lo < hi) {
        int mid = (lo + hi) >> 1;
        if (s_start[mid] <= j0) lo = mid + 1; else hi = mid;
    }
    int cur = lo - 1;

    int4 m;
    int mv[4];
    #pragma unroll
    for (int c = 0; c < 4; c++) {
        const int j = j0 + c;
        if (j >= s_start[cur + 1]) cur++;    // at most one boundary in 4 cols
        const int s = s_start[cur];
        const int e = s_end[cur];
        int o = -2;                           // zero fill
        if (j < e)                      o = s_src[cur] + (j - s);
        else if (j == e && cur < n - 1) o = -1;  // separator
        mv[c] = o;
    }
    m.x = mv[0]; m.y = mv[1]; m.z = mv[2]; m.w = mv[3];
    *reinterpret_cast<int4*>(&g_map[b][j0]) = m;
}

// ---------------------------------------------------------------------------
// Kernel 3: pack/gather. grid = (8, 16, 16) = 2048 blocks, block = 256.
// NO shared memory, NO syncthreads, NO searches: one int4 map load, then
// 8 rows of {4 predicated gather LDGs + 1 STG.128}.
// ---------------------------------------------------------------------------
__global__ void __launch_bounds__(256)
pack_kernel(const float* __restrict__ x,
            const float* __restrict__ sep_param,
            float* __restrict__ out) {
    const int b  = blockIdx.y;
    const int t  = threadIdx.x;
    const int j0 = (blockIdx.x * 256 + t) * 4;

    const int4 m = *reinterpret_cast<const int4*>(&g_map[b][j0]);
    const float sep = __ldg(sep_param);

    const bool g0 = m.x >= 0, g1 = m.y >= 0, g2 = m.z >= 0, g3 = m.w >= 0;
    const float f0 = (m.x == -1) ? sep : 0.0f;
    const float f1 = (m.y == -1) ? sep : 0.0f;
    const float f2 = (m.z == -1) ? sep : 0.0f;
    const float f3 = (m.w == -1) ? sep : 0.0f;

    const int h0 = blockIdx.z * ROWS_PER_BLOCK;
    const float* __restrict__ xb = x   + (size_t)b * HH * WW + (size_t)h0 * WW;
    float* __restrict__       ob = out + (size_t)b * HH * WW + (size_t)h0 * WW;

    #pragma unroll 2
    for (int hh = 0; hh < ROWS_PER_BLOCK; hh++) {
        const size_t row = (size_t)hh * WW;
        float4 v;
        v.x = g0 ? __ldg(xb + row + m.x) : f0;
        v.y = g1 ? __ldg(xb + row + m.y) : f1;
        v.z = g2 ? __ldg(xb + row + m.z) : f2;
        v.w = g3 ? __ldg(xb + row + m.w) : f3;
        __stcs(reinterpret_cast<float4*>(ob + row + j0), v);
    }
}

// ---------------------------------------------------------------------------
extern "C" void kernel_launch(void* const* d_in, const int* in_sizes, int n_in,
                              void* d_out, int out_size) {
    const float* x   = (const float*)d_in[0];
    const int*   xi  = (const int*)  d_in[1];
    const int*   N   = (const int*)  d_in[2];
    const float* sep = (const float*)d_in[3];
    float*       out = (float*)d_out;

    const long long XN = (long long)BB * HH * WW;   // 16,777,216
    const int write_xi = ((long long)out_size > XN) ? 1 : 0;

    meta_kernel<<<BB, NMX>>>(xi, N, out + XN, write_xi);

    dim3 mgrid(BB, WW / (256 * 4));
    map_kernel<<<mgrid, 256>>>();

    dim3 grid(WW / (256 * 4), BB, HH / ROWS_PER_BLOCK);
    pack_kernel<<<grid, 256>>>(x, sep, out);
}